// round 5
// baseline (speedup 1.0000x reference)
#include <cuda_runtime.h>
#include <cstdint>

#define H 2048
#define B 16
#define S 256
#define V 32000
#define NBLK 128
#define NTHR 512

typedef unsigned long long ull;

__device__ float g_gamma_exp[H];
__device__ float g_E[2][H * B];        // exp(y_t - shift_t), double buffered by t&1
__device__ float g_part[2][NBLK * B];  // per-block row maxes of y_t
__device__ unsigned g_flag[NBLK];      // block published step t => flag == t+1

__device__ __forceinline__ ull splat2(float v) {
    ull r; asm("mov.b64 %0, {%1, %1};" : "=l"(r) : "f"(v)); return r;
}
__device__ __forceinline__ ull fma2(ull a, ull b, ull c) {
    ull d; asm("fma.rn.f32x2 %0, %1, %2, %3;" : "=l"(d) : "l"(a), "l"(b), "l"(c)); return d;
}
__device__ __forceinline__ ull add2(ull a, ull b) {
    ull d; asm("add.rn.f32x2 %0, %1, %2;" : "=l"(d) : "l"(a), "l"(b)); return d;
}
__device__ __forceinline__ void upk(ull v, float& lo, float& hi) {
    asm("mov.b64 {%0, %1}, %2;" : "=f"(lo), "=f"(hi) : "l"(v));
}
__device__ __forceinline__ ull shflx16(ull v) {
    unsigned lo = (unsigned)v, hi = (unsigned)(v >> 32);
    lo = __shfl_xor_sync(0xffffffffu, lo, 16);
    hi = __shfl_xor_sync(0xffffffffu, hi, 16);
    return ((ull)hi << 32) | lo;
}
__device__ __forceinline__ unsigned ld_acq(const unsigned* p) {
    unsigned v;
    asm volatile("ld.acquire.gpu.global.u32 %0, [%1];" : "=r"(v) : "l"(p) : "memory");
    return v;
}
__device__ __forceinline__ void st_rel(unsigned* p, unsigned v) {
    asm volatile("st.release.gpu.global.u32 [%0], %1;" :: "l"(p), "r"(v) : "memory");
}

// ---------------------------------------------------------------------------
__global__ void init_flags_kernel() {
    if (threadIdx.x < NBLK) g_flag[threadIdx.x] = 0u;
}

// ---------------------------------------------------------------------------
__global__ void gamma_kernel(const float* __restrict__ gamma) {
    __shared__ float red[256];
    __shared__ float s_max, s_sum;
    int tid = threadIdx.x;
    float mx = -3.4e38f;
    for (int i = tid; i < H; i += 256) mx = fmaxf(mx, gamma[i]);
    red[tid] = mx;
    __syncthreads();
    for (int o = 128; o > 0; o >>= 1) {
        if (tid < o) red[tid] = fmaxf(red[tid], red[tid + o]);
        __syncthreads();
    }
    if (tid == 0) s_max = red[0];
    __syncthreads();
    float m = s_max;
    float sm = 0.f;
    for (int i = tid; i < H; i += 256) sm += __expf(gamma[i] - m);
    __syncthreads();
    red[tid] = sm;
    __syncthreads();
    for (int o = 128; o > 0; o >>= 1) {
        if (tid < o) red[tid] += red[tid + o];
        __syncthreads();
    }
    if (tid == 0) s_sum = red[0];
    __syncthreads();
    float inv = 1.0f / s_sum;
    for (int i = tid; i < H; i += 256) g_gamma_exp[i] = __expf(gamma[i] - m) * inv;
}

// ---------------------------------------------------------------------------
// persistent kernel: t=0 init + 255 recurrence steps, per-warp producer flags
// ---------------------------------------------------------------------------
__global__ void __launch_bounds__(NTHR, 1) hmm_persist(
    const int* __restrict__ ids, const float* __restrict__ alpha,
    const float* __restrict__ beta, float* __restrict__ out) {
    extern __shared__ float smem[];
    float* s_a = smem;                 // [2048][16]  alpha slice, [k][r] (131072B)
    float* s_part = s_a + H * 16;      // [256][16]   k-slice partials (16KB)
    float* s_y = s_part + 256 * 16;    // [256]
    float* s_m = s_y + 256;            // [16]  shift for publishing E_t   (= m_{t-1})
    float* s_old = s_m + 16;           // [16]  shift used in E_{t-1}      (= m_{t-2})
    float* s_red = s_old + 16;         // [16][16]

    const int tid = threadIdx.x;
    const int blk = blockIdx.x;
    const int r0 = blk * 16;
    const int lane = tid & 31, w = tid >> 5;
    const int bg = lane & 3;           // 4 b's: bg*4..bg*4+3
    const int rg = (lane >> 2) & 3;    // 4 rows: rg*4..rg*4+3
    const int khalf = lane >> 4;       // k parity within warp's 128-k range
    const int orow = tid >> 4, ob = tid & 15;  // epilogue mapping (tid<256)

    // stage alpha slice transposed: s_a[k*16 + rl] = alpha[(r0+rl)*H + k]
    for (int rl = 0; rl < 16; rl++) {
        const float* ap = alpha + (size_t)(r0 + rl) * H;
        for (int k = tid; k < H; k += NTHR) s_a[k * 16 + rl] = __ldg(ap + k);
    }
    if (tid < 16) s_m[tid] = 0.f;
    __syncthreads();

    // ---- t = 0: y0 = masked beta gather; E_0 uses shift 0 (y0 <= 0)
    {
        if (tid < 256) {
            int id = __ldg(&ids[ob * S + (S - 1)]);
            float bv = __ldg(&beta[(size_t)(r0 + orow) * V + (id < 0 ? 0 : id)]);
            float y0 = (id < 0) ? 0.f : bv;
            out[(size_t)(r0 + orow) * B + ob] = y0;
            s_y[tid] = y0;
            g_E[0][(r0 + orow) * B + ob] = __expf(y0);
        }
        __syncthreads();
        if (tid < 16) {
            float mx = s_y[tid];
            #pragma unroll
            for (int rr = 1; rr < 16; rr++) mx = fmaxf(mx, s_y[rr * 16 + tid]);
            g_part[0][blk * B + tid] = mx;
        }
        __threadfence();
        __syncthreads();
        if (tid == 0) st_rel(&g_flag[blk], 1u);
    }

    // ---- main recurrence
    for (int t = 1; t < S; t++) {
        const int par = (t - 1) & 1;

        // prefetch ip (independent of any flag)
        float ipv = 0.f;
        if (tid < 256) {
            int id = __ldg(&ids[ob * S + (S - 1 - t)]);
            float bv = __ldg(&beta[(size_t)(r0 + orow) * V + (id < 0 ? 0 : id)]);
            ipv = (id < 0) ? 0.f : bv;
        }

        // save previous shift (sync'd by prior step's final barrier)
        if (tid < 16) s_old[tid] = s_m[tid];

        // per-warp wait: only this warp's 8 producer blocks must have published t-1
        if (lane < 8) {
            const unsigned* fp = &g_flag[w * 8 + lane];
            while (ld_acq(fp) < (unsigned)t) {}
        }
        __syncwarp();

        // ---- dot: acc[rl][bp] over this warp's 128 k values (64 per khalf)
        const float* Eg = g_E[par];
        ull acc[4][2];
        #pragma unroll
        for (int l = 0; l < 4; l++) { acc[l][0] = 0ull; acc[l][1] = 0ull; }

        const int kbase = w * 128 + khalf;
        #pragma unroll 16
        for (int i = 0; i < 64; i++) {
            const int k = kbase + 2 * i;
            ulonglong2 ev = __ldcg(reinterpret_cast<const ulonglong2*>(Eg + k * 16 + bg * 4));
            float4 av = *reinterpret_cast<const float4*>(s_a + k * 16 + rg * 4);
            ull a0 = splat2(av.x), a1 = splat2(av.y), a2 = splat2(av.z), a3 = splat2(av.w);
            acc[0][0] = fma2(a0, ev.x, acc[0][0]);
            acc[0][1] = fma2(a0, ev.y, acc[0][1]);
            acc[1][0] = fma2(a1, ev.x, acc[1][0]);
            acc[1][1] = fma2(a1, ev.y, acc[1][1]);
            acc[2][0] = fma2(a2, ev.x, acc[2][0]);
            acc[2][1] = fma2(a2, ev.y, acc[2][1]);
            acc[3][0] = fma2(a3, ev.x, acc[3][0]);
            acc[3][1] = fma2(a3, ev.y, acc[3][1]);
        }

        // combine khalf halves within warp
        #pragma unroll
        for (int l = 0; l < 4; l++) {
            acc[l][0] = add2(acc[l][0], shflx16(acc[l][0]));
            acc[l][1] = add2(acc[l][1], shflx16(acc[l][1]));
        }
        if (khalf == 0) {
            #pragma unroll
            for (int l = 0; l < 4; l++) {
                float f0, f1;
                upk(acc[l][0], f0, f1);
                s_part[((rg * 4 + l) * 16 + bg * 4 + 0) * 16 + w] = f0;
                s_part[((rg * 4 + l) * 16 + bg * 4 + 1) * 16 + w] = f1;
                upk(acc[l][1], f0, f1);
                s_part[((rg * 4 + l) * 16 + bg * 4 + 2) * 16 + w] = f0;
                s_part[((rg * 4 + l) * 16 + bg * 4 + 3) * 16 + w] = f1;
            }
        }
        __syncthreads();  // all dots done => collectively all 128 flags observed >= t

        // m_{t-1} = max over all blocks' row maxes (off critical path now)
        if (tid < 256) {
            int g = tid >> 4;
            const float* gp = g_part[par];
            float mx = -3.4e38f;
            #pragma unroll
            for (int j = 0; j < 8; j++) mx = fmaxf(mx, __ldcg(gp + (g * 8 + j) * B + ob));
            s_red[g * 16 + ob] = mx;
        }
        __syncthreads();
        if (tid < 16) {
            float mx = s_red[tid];
            #pragma unroll
            for (int g = 1; g < 16; g++) mx = fmaxf(mx, s_red[g * 16 + tid]);
            s_m[tid] = mx;
        }
        __syncthreads();

        // epilogue: reduce 16 warps, log, add shift + ip, publish
        if (tid < 256) {
            const float* pp = s_part + tid * 16;
            float sum = 0.f;
            #pragma unroll
            for (int c = 0; c < 16; c++) sum += pp[c];
            float y = __logf(sum) + s_old[ob] + ipv;
            out[(size_t)t * H * B + (size_t)(r0 + orow) * B + ob] = y;
            s_y[tid] = y;
            g_E[t & 1][(r0 + orow) * B + ob] = __expf(y - s_m[ob]);
        }
        __syncthreads();
        if (tid < 16) {
            float mx = s_y[tid];
            #pragma unroll
            for (int rr = 1; rr < 16; rr++) mx = fmaxf(mx, s_y[rr * 16 + tid]);
            g_part[t & 1][blk * B + tid] = mx;
        }
        __threadfence();
        __syncthreads();
        if (tid == 0) st_rel(&g_flag[blk], (unsigned)(t + 1));
    }
}

// ---------------------------------------------------------------------------
// final[b] = log(gamma_exp . exp(y_last[:,b] - m_b)) + m_b
// 512 threads: stage y_last into padded smem, then warp-per-b shfl reduce
// ---------------------------------------------------------------------------
__global__ void __launch_bounds__(NTHR) final_kernel(float* __restrict__ out) {
    extern __shared__ float s_yl[];  // [2048][17] padded
    const int tid = threadIdx.x;
    const int lane = tid & 31, w = tid >> 5;  // w = batch index (16 warps)
    const float* __restrict__ yl = out + (size_t)(S - 1) * H * B;

    #pragma unroll 8
    for (int i = tid; i < H * B; i += NTHR) {
        int h = i >> 4, b = i & 15;
        s_yl[h * 17 + b] = __ldcg(yl + i);
    }
    __syncthreads();

    float mx = -3.4e38f;
    #pragma unroll 8
    for (int h = lane; h < H; h += 32) mx = fmaxf(mx, s_yl[h * 17 + w]);
    #pragma unroll
    for (int o = 16; o > 0; o >>= 1) mx = fmaxf(mx, __shfl_xor_sync(0xffffffffu, mx, o));

    float sm = 0.f;
    #pragma unroll 8
    for (int h = lane; h < H; h += 32)
        sm += g_gamma_exp[h] * __expf(s_yl[h * 17 + w] - mx);
    #pragma unroll
    for (int o = 16; o > 0; o >>= 1) sm += __shfl_xor_sync(0xffffffffu, sm, o);

    if (lane == 0) out[(size_t)S * H * B + w] = __logf(sm) + mx;
}

// ---------------------------------------------------------------------------
extern "C" void kernel_launch(void* const* d_in, const int* in_sizes, int n_in,
                              void* d_out, int out_size) {
    const int* ids = (const int*)d_in[0];        // (B, S) int32
    const float* alpha = (const float*)d_in[1];  // (H, H)
    const float* beta = (const float*)d_in[2];   // (H, V)
    const float* gamma = (const float*)d_in[3];  // (H,)
    float* out = (float*)d_out;                  // ys (S,H,B) then final (B,)

    const int smem_main = (H * 16 + 256 * 16 + 256 + 16 + 16 + 256) * (int)sizeof(float);
    const int smem_final = H * 17 * (int)sizeof(float);
    cudaFuncSetAttribute(hmm_persist, cudaFuncAttributeMaxDynamicSharedMemorySize, smem_main);
    cudaFuncSetAttribute(final_kernel, cudaFuncAttributeMaxDynamicSharedMemorySize, smem_final);

    init_flags_kernel<<<1, 128>>>();
    gamma_kernel<<<1, 256>>>(gamma);
    hmm_persist<<<NBLK, NTHR, smem_main>>>(ids, alpha, beta, out);
    final_kernel<<<1, NTHR, smem_final>>>(out);
}

// round 6
// speedup vs baseline: 1.1076x; 1.1076x over previous
#include <cuda_runtime.h>
#include <cstdint>

#define H 2048
#define B 16
#define S 256
#define V 32000
#define NBLK 128
#define NTHR 512

typedef unsigned long long ull;

__device__ float g_gamma_exp[H];
__device__ float g_E[2][H * B];        // exp(y_t - m_blk) per producer block, buffered by t&1
__device__ float g_part[2][NBLK * B];  // per-block per-b row maxes of y_t
__device__ unsigned g_flag[NBLK];      // block published step t => flag == t+1

__device__ __forceinline__ ull splat2(float v) {
    ull r; asm("mov.b64 %0, {%1, %1};" : "=l"(r) : "f"(v)); return r;
}
__device__ __forceinline__ ull pack2(float lo, float hi) {
    ull r; asm("mov.b64 %0, {%1, %2};" : "=l"(r) : "f"(lo), "f"(hi)); return r;
}
__device__ __forceinline__ ull fma2(ull a, ull b, ull c) {
    ull d; asm("fma.rn.f32x2 %0, %1, %2, %3;" : "=l"(d) : "l"(a), "l"(b), "l"(c)); return d;
}
__device__ __forceinline__ ull mul2(ull a, ull b) {
    ull d; asm("mul.rn.f32x2 %0, %1, %2;" : "=l"(d) : "l"(a), "l"(b)); return d;
}
__device__ __forceinline__ ull add2(ull a, ull b) {
    ull d; asm("add.rn.f32x2 %0, %1, %2;" : "=l"(d) : "l"(a), "l"(b)); return d;
}
__device__ __forceinline__ void upk(ull v, float& lo, float& hi) {
    asm("mov.b64 {%0, %1}, %2;" : "=f"(lo), "=f"(hi) : "l"(v));
}
__device__ __forceinline__ ull shflx16(ull v) {
    unsigned lo = (unsigned)v, hi = (unsigned)(v >> 32);
    lo = __shfl_xor_sync(0xffffffffu, lo, 16);
    hi = __shfl_xor_sync(0xffffffffu, hi, 16);
    return ((ull)hi << 32) | lo;
}
__device__ __forceinline__ unsigned ld_acq(const unsigned* p) {
    unsigned v;
    asm volatile("ld.acquire.gpu.global.u32 %0, [%1];" : "=r"(v) : "l"(p) : "memory");
    return v;
}
__device__ __forceinline__ void st_rel(unsigned* p, unsigned v) {
    asm volatile("st.release.gpu.global.u32 [%0], %1;" :: "l"(p), "r"(v) : "memory");
}

// ---------------------------------------------------------------------------
__global__ void init_flags_kernel() {
    if (threadIdx.x < NBLK) g_flag[threadIdx.x] = 0u;
}

// ---------------------------------------------------------------------------
__global__ void gamma_kernel(const float* __restrict__ gamma) {
    __shared__ float red[256];
    __shared__ float s_max, s_sum;
    int tid = threadIdx.x;
    float mx = -3.4e38f;
    for (int i = tid; i < H; i += 256) mx = fmaxf(mx, gamma[i]);
    red[tid] = mx;
    __syncthreads();
    for (int o = 128; o > 0; o >>= 1) {
        if (tid < o) red[tid] = fmaxf(red[tid], red[tid + o]);
        __syncthreads();
    }
    if (tid == 0) s_max = red[0];
    __syncthreads();
    float m = s_max;
    float sm = 0.f;
    for (int i = tid; i < H; i += 256) sm += __expf(gamma[i] - m);
    __syncthreads();
    red[tid] = sm;
    __syncthreads();
    for (int o = 128; o > 0; o >>= 1) {
        if (tid < o) red[tid] += red[tid + o];
        __syncthreads();
    }
    if (tid == 0) s_sum = red[0];
    __syncthreads();
    float inv = 1.0f / s_sum;
    for (int i = tid; i < H; i += 256) g_gamma_exp[i] = __expf(gamma[i] - m) * inv;
}

// ---------------------------------------------------------------------------
// persistent kernel: t=0 init + 255 steps (per-block-shift E, flash-style
// consumer rescaling) + final reduction folded in (blocks 0..15)
// ---------------------------------------------------------------------------
__global__ void __launch_bounds__(NTHR, 1) hmm_persist(
    const int* __restrict__ ids, const float* __restrict__ alpha,
    const float* __restrict__ beta, float* __restrict__ out) {
    extern __shared__ float smem[];
    float* s_a = smem;               // [2048][16] alpha slice [k][r]   (131072B)
    float* s_part = s_a + H * 16;    // [256 rows*b][16 warps] partials (16KB)
    float* s_y = s_part + 256 * 16;  // [256]
    float* s_mw = s_y + 256;         // [16 warps][16 b] warp frames
    float* s_mb = s_mw + 256;        // [16]  own-block row max

    const int tid = threadIdx.x;
    const int blk = blockIdx.x;
    const int r0 = blk * 16;
    const int lane = tid & 31, w = tid >> 5;
    const int bg = lane & 3;                   // b group: b = bg*4..bg*4+3
    const int rg = (lane >> 2) & 3;            // row group: rows rg*4..rg*4+3
    const int khalf = lane >> 4;               // k parity in warp's 128-k slice
    const int orow = tid >> 4, ob = tid & 15;  // epilogue mapping (tid<256)

    // stage alpha slice transposed: s_a[k*16 + rl] = alpha[(r0+rl)*H + k]
    for (int rl = 0; rl < 16; rl++) {
        const float* ap = alpha + (size_t)(r0 + rl) * H;
        for (int k = tid; k < H; k += NTHR) s_a[k * 16 + rl] = __ldg(ap + k);
    }
    __syncthreads();

    // ---- publish helper body used for t=0 and each step (inlined manually)
    // t = 0: y0 = masked beta gather
    {
        float y0 = 0.f;
        if (tid < 256) {
            int id = __ldg(&ids[ob * S + (S - 1)]);
            float bv = __ldg(&beta[(size_t)(r0 + orow) * V + (id < 0 ? 0 : id)]);
            y0 = (id < 0) ? 0.f : bv;
            out[(size_t)(r0 + orow) * B + ob] = y0;
            s_y[tid] = y0;
        }
        __syncthreads();
        if (tid < 16) {
            float mx = s_y[tid];
            #pragma unroll
            for (int rr = 1; rr < 16; rr++) mx = fmaxf(mx, s_y[rr * 16 + tid]);
            s_mb[tid] = mx;
            g_part[0][blk * B + tid] = mx;
        }
        __syncthreads();
        if (tid < 256)
            g_E[0][(r0 + orow) * B + ob] = __expf(y0 - s_mb[ob]);
        __threadfence();
        __syncthreads();
        if (tid == 0) st_rel(&g_flag[blk], 1u);
    }

    // ---- main recurrence
    for (int t = 1; t < S; t++) {
        const int par = (t - 1) & 1;

        // prefetch ip (independent of any flag)
        float ipv = 0.f;
        if (tid < 256) {
            int id = __ldg(&ids[ob * S + (S - 1 - t)]);
            float bv = __ldg(&beta[(size_t)(r0 + orow) * V + (id < 0 ? 0 : id)]);
            ipv = (id < 0) ? 0.f : bv;
        }

        // per-warp wait: this warp's 8 producer blocks (rows 128w..128w+127)
        if (lane < 8) {
            const unsigned* fp = &g_flag[w * 8 + lane];
            if (ld_acq(fp) < (unsigned)t) {
                do { __nanosleep(32); } while (ld_acq(fp) < (unsigned)t);
            }
        }
        __syncwarp();

        // load the 8 producer frames for this thread's 4 b's, build warp frame
        float4 mj[8];
        #pragma unroll
        for (int j = 0; j < 8; j++)
            mj[j] = __ldcg(reinterpret_cast<const float4*>(
                g_part[par] + (w * 8 + j) * B + bg * 4));
        float M0 = mj[0].x, M1 = mj[0].y, M2 = mj[0].z, M3 = mj[0].w;
        #pragma unroll
        for (int j = 1; j < 8; j++) {
            M0 = fmaxf(M0, mj[j].x); M1 = fmaxf(M1, mj[j].y);
            M2 = fmaxf(M2, mj[j].z); M3 = fmaxf(M3, mj[j].w);
        }
        ull fx[8], fy[8];
        #pragma unroll
        for (int j = 0; j < 8; j++) {
            fx[j] = pack2(__expf(mj[j].x - M0), __expf(mj[j].y - M1));
            fy[j] = pack2(__expf(mj[j].z - M2), __expf(mj[j].w - M3));
        }

        // ---- dot over this warp's 128 k (64 per khalf), chunk-rescaled
        const float* Eg = g_E[par];
        ull acc[4][2];
        #pragma unroll
        for (int l = 0; l < 4; l++) { acc[l][0] = 0ull; acc[l][1] = 0ull; }

        const int kbase = w * 128 + khalf;
        #pragma unroll
        for (int j = 0; j < 8; j++) {
            const ull fxx = fx[j], fyy = fy[j];
            #pragma unroll
            for (int i2 = 0; i2 < 8; i2++) {
                const int k = kbase + j * 16 + 2 * i2;
                ulonglong2 ev =
                    __ldcg(reinterpret_cast<const ulonglong2*>(Eg + k * B + bg * 4));
                const ull ex = mul2(ev.x, fxx);
                const ull ey = mul2(ev.y, fyy);
                float4 av = *reinterpret_cast<const float4*>(s_a + k * 16 + rg * 4);
                const ull a0 = splat2(av.x), a1 = splat2(av.y);
                const ull a2 = splat2(av.z), a3 = splat2(av.w);
                acc[0][0] = fma2(a0, ex, acc[0][0]);
                acc[0][1] = fma2(a0, ey, acc[0][1]);
                acc[1][0] = fma2(a1, ex, acc[1][0]);
                acc[1][1] = fma2(a1, ey, acc[1][1]);
                acc[2][0] = fma2(a2, ex, acc[2][0]);
                acc[2][1] = fma2(a2, ey, acc[2][1]);
                acc[3][0] = fma2(a3, ex, acc[3][0]);
                acc[3][1] = fma2(a3, ey, acc[3][1]);
            }
        }

        // combine khalf halves, store partials + warp frame
        #pragma unroll
        for (int l = 0; l < 4; l++) {
            acc[l][0] = add2(acc[l][0], shflx16(acc[l][0]));
            acc[l][1] = add2(acc[l][1], shflx16(acc[l][1]));
        }
        if (khalf == 0) {
            #pragma unroll
            for (int l = 0; l < 4; l++) {
                float f0, f1;
                upk(acc[l][0], f0, f1);
                s_part[((rg * 4 + l) * 16 + bg * 4 + 0) * 16 + w] = f0;
                s_part[((rg * 4 + l) * 16 + bg * 4 + 1) * 16 + w] = f1;
                upk(acc[l][1], f0, f1);
                s_part[((rg * 4 + l) * 16 + bg * 4 + 2) * 16 + w] = f0;
                s_part[((rg * 4 + l) * 16 + bg * 4 + 3) * 16 + w] = f1;
            }
            if (rg == 0) {
                float4 Mv = make_float4(M0, M1, M2, M3);
                *reinterpret_cast<float4*>(s_mw + w * 16 + bg * 4) = Mv;
            }
        }
        __syncthreads();

        // epilogue: combine 16 warp partials with frame correction
        float y = 0.f;
        if (tid < 256) {
            float Mb = s_mw[0 * 16 + ob];
            #pragma unroll
            for (int c = 1; c < 16; c++) Mb = fmaxf(Mb, s_mw[c * 16 + ob]);
            const float* pp = s_part + tid * 16;
            float sum = 0.f;
            #pragma unroll
            for (int c = 0; c < 16; c++)
                sum += pp[c] * __expf(s_mw[c * 16 + ob] - Mb);
            y = __logf(sum) + Mb + ipv;
            out[(size_t)t * H * B + (size_t)(r0 + orow) * B + ob] = y;
            s_y[tid] = y;
        }
        __syncthreads();
        if (tid < 16) {
            float mx = s_y[tid];
            #pragma unroll
            for (int rr = 1; rr < 16; rr++) mx = fmaxf(mx, s_y[rr * 16 + tid]);
            s_mb[tid] = mx;
            g_part[t & 1][blk * B + tid] = mx;
        }
        __syncthreads();
        if (tid < 256)
            g_E[t & 1][(r0 + orow) * B + ob] = __expf(y - s_mb[ob]);
        __threadfence();
        __syncthreads();
        if (tid == 0) st_rel(&g_flag[blk], (unsigned)(t + 1));
    }

    // ---- final reduction folded in: block b (< 16) computes final[b]
    if (blk < 16) {
        if (tid < NBLK) {
            const unsigned* fp = &g_flag[tid];
            if (ld_acq(fp) < (unsigned)S) {
                do { __nanosleep(32); } while (ld_acq(fp) < (unsigned)S);
            }
        }
        __syncthreads();
        const float* yl = out + (size_t)(S - 1) * H * B;
        float v[4], g[4];
        #pragma unroll
        for (int i = 0; i < 4; i++) {
            int h = tid + i * NTHR;
            v[i] = __ldcg(yl + (size_t)h * B + blk);
            g[i] = g_gamma_exp[h];
        }
        float mx = fmaxf(fmaxf(v[0], v[1]), fmaxf(v[2], v[3]));
        #pragma unroll
        for (int o = 16; o > 0; o >>= 1)
            mx = fmaxf(mx, __shfl_xor_sync(0xffffffffu, mx, o));
        if (lane == 0) s_part[w] = mx;
        __syncthreads();
        if (tid < 16) {
            float m2 = s_part[tid];
            #pragma unroll
            for (int o = 8; o > 0; o >>= 1)
                m2 = fmaxf(m2, __shfl_xor_sync(0xffffu, m2, o));
            s_mb[0] = m2;  // lane0 writes final max
        }
        __syncthreads();
        const float M = s_mb[0];
        float sm = 0.f;
        #pragma unroll
        for (int i = 0; i < 4; i++) sm += g[i] * __expf(v[i] - M);
        #pragma unroll
        for (int o = 16; o > 0; o >>= 1) sm += __shfl_xor_sync(0xffffffffu, sm, o);
        if (lane == 0) s_part[w] = sm;
        __syncthreads();
        if (tid == 0) {
            float tot = 0.f;
            #pragma unroll
            for (int c = 0; c < 16; c++) tot += s_part[c];
            out[(size_t)S * H * B + blk] = __logf(tot) + M;
        }
    }
}

// ---------------------------------------------------------------------------
extern "C" void kernel_launch(void* const* d_in, const int* in_sizes, int n_in,
                              void* d_out, int out_size) {
    const int* ids = (const int*)d_in[0];        // (B, S) int32
    const float* alpha = (const float*)d_in[1];  // (H, H)
    const float* beta = (const float*)d_in[2];   // (H, V)
    const float* gamma = (const float*)d_in[3];  // (H,)
    float* out = (float*)d_out;                  // ys (S,H,B) then final (B,)

    const int smem_main =
        (H * 16 + 256 * 16 + 256 + 256 + 16) * (int)sizeof(float);
    cudaFuncSetAttribute(hmm_persist, cudaFuncAttributeMaxDynamicSharedMemorySize,
                         smem_main);

    init_flags_kernel<<<1, 128>>>();
    gamma_kernel<<<1, 256>>>(gamma);
    hmm_persist<<<NBLK, NTHR, smem_main>>>(ids, alpha, beta, out);
}